// round 1
// baseline (speedup 1.0000x reference)
#include <cuda_runtime.h>
#include <math.h>

#define B_  32
#define C_  512
#define HW  1024
#define GRP 32
#define CPG 16      // channels per group
#define EPS 1e-5f

// Scratch (allocation-free rule: __device__ globals)
__device__ float g_hn[(size_t)B_ * C_ * HW];
__device__ float g_q [(size_t)B_ * C_ * HW];
__device__ float g_k [(size_t)B_ * C_ * HW];
__device__ float g_v [(size_t)B_ * C_ * HW];
__device__ float g_o [(size_t)B_ * C_ * HW];
__device__ float g_attn[(size_t)B_ * HW * HW];

// ---------------------------------------------------------------------------
// GroupNorm: one block per (batch, group). 16 ch x 1024 = 16384 elements.
// ---------------------------------------------------------------------------
__global__ __launch_bounds__(256) void gn_kernel(
    const float* __restrict__ x, const float* __restrict__ scale,
    const float* __restrict__ bias, float* __restrict__ hn)
{
    int b = blockIdx.x >> 5;
    int g = blockIdx.x & 31;
    const int n = CPG * HW;            // 16384
    size_t base = ((size_t)b * C_ + (size_t)g * CPG) * HW;
    const float4* x4 = (const float4*)(x + base);
    int n4 = n / 4;                    // 4096

    float s = 0.f, ss = 0.f;
    for (int i = threadIdx.x; i < n4; i += 256) {
        float4 v = x4[i];
        s  += v.x + v.y + v.z + v.w;
        ss += v.x * v.x + v.y * v.y + v.z * v.z + v.w * v.w;
    }
    __shared__ float sh_s[256], sh_ss[256];
    sh_s[threadIdx.x] = s; sh_ss[threadIdx.x] = ss;
    __syncthreads();
    for (int off = 128; off > 0; off >>= 1) {
        if (threadIdx.x < off) {
            sh_s[threadIdx.x]  += sh_s[threadIdx.x + off];
            sh_ss[threadIdx.x] += sh_ss[threadIdx.x + off];
        }
        __syncthreads();
    }
    float mean = sh_s[0] * (1.f / n);
    float var  = sh_ss[0] * (1.f / n) - mean * mean;
    float inv  = rsqrtf(var + EPS);

    float4* hn4 = (float4*)(hn + base);
    for (int i = threadIdx.x; i < n4; i += 256) {
        int ch = g * CPG + ((i * 4) >> 10);     // HW = 1024
        float a = scale[ch] * inv;
        float c = bias[ch] - mean * a;
        float4 v = x4[i];
        v.x = v.x * a + c; v.y = v.y * a + c;
        v.z = v.z * a + c; v.w = v.w * a + c;
        hn4[i] = v;
    }
}

// ---------------------------------------------------------------------------
// Generic batched SGEMM:  C[m,n] = alpha * sum_k A(m,k)*B(k,n) [+bias[m]] [+R[m,n]]
//   A_KM  : A stored [K,M] (contiguous in m), else [M,K] (contiguous in k)
//   B_NK  : B stored [N,K] (contiguous in k), else [K,N] (contiguous in n)
// BM=BN=128, BK=16, 256 threads, 8x8 per thread.
// ---------------------------------------------------------------------------
template<bool A_KM, bool B_NK, bool BIAS, bool RES>
__global__ __launch_bounds__(256) void gemm_kernel(
    const float* __restrict__ A, const float* __restrict__ Bm,
    float* __restrict__ Cm,
    const float* __restrict__ bias, const float* __restrict__ R,
    int M, int N, int K,
    size_t sA, size_t sB, size_t sC, size_t sR, float alpha)
{
    constexpr int BK = 16;
    __shared__ float As[BK][128];
    __shared__ float Bs[BK][128];

    int bz = blockIdx.z;
    A  += sA * bz;  Bm += sB * bz;  Cm += sC * bz;
    if (RES) R += sR * bz;

    int m0 = blockIdx.y * 128, n0 = blockIdx.x * 128;
    int tid = threadIdx.x;
    int tm = (tid >> 4) * 8, tn = (tid & 15) * 8;

    float acc[8][8];
    #pragma unroll
    for (int i = 0; i < 8; i++)
        #pragma unroll
        for (int j = 0; j < 8; j++) acc[i][j] = 0.f;

    for (int k0 = 0; k0 < K; k0 += BK) {
        #pragma unroll
        for (int i = 0; i < 8; i++) {
            int idx = tid + i * 256;
            if (A_KM) {
                int mm = idx & 127, kk = idx >> 7;
                As[kk][mm] = A[(size_t)(k0 + kk) * M + (m0 + mm)];
            } else {
                int kk = idx & 15, mm = idx >> 4;
                As[kk][mm] = A[(size_t)(m0 + mm) * K + (k0 + kk)];
            }
        }
        #pragma unroll
        for (int i = 0; i < 8; i++) {
            int idx = tid + i * 256;
            if (!B_NK) {
                int nn = idx & 127, kk = idx >> 7;
                Bs[kk][nn] = Bm[(size_t)(k0 + kk) * N + (n0 + nn)];
            } else {
                int kk = idx & 15, nn = idx >> 4;
                Bs[kk][nn] = Bm[(size_t)(n0 + nn) * K + (k0 + kk)];
            }
        }
        __syncthreads();

        #pragma unroll
        for (int kk = 0; kk < BK; kk++) {
            float4 a0 = *(const float4*)&As[kk][tm];
            float4 a1 = *(const float4*)&As[kk][tm + 4];
            float4 b0 = *(const float4*)&Bs[kk][tn];
            float4 b1 = *(const float4*)&Bs[kk][tn + 4];
            float a[8] = {a0.x, a0.y, a0.z, a0.w, a1.x, a1.y, a1.z, a1.w};
            float b[8] = {b0.x, b0.y, b0.z, b0.w, b1.x, b1.y, b1.z, b1.w};
            #pragma unroll
            for (int i = 0; i < 8; i++)
                #pragma unroll
                for (int j = 0; j < 8; j++)
                    acc[i][j] += a[i] * b[j];
        }
        __syncthreads();
    }

    #pragma unroll
    for (int i = 0; i < 8; i++) {
        int m = m0 + tm + i;
        float bi = BIAS ? bias[m] : 0.f;
        #pragma unroll
        for (int j = 0; j < 8; j++) {
            int n = n0 + tn + j;
            float v = acc[i][j] * alpha + bi;
            if (RES) v += R[(size_t)m * N + n];
            Cm[(size_t)m * N + n] = v;
        }
    }
}

// ---------------------------------------------------------------------------
// Row softmax: one block per row of 1024.
// ---------------------------------------------------------------------------
__global__ __launch_bounds__(256) void softmax_kernel(float* __restrict__ attn)
{
    size_t row = blockIdx.x;
    float4* p4 = (float4*)(attn + row * HW);
    int tid = threadIdx.x;
    float4 v = p4[tid];

    __shared__ float sh[256];
    float m = fmaxf(fmaxf(v.x, v.y), fmaxf(v.z, v.w));
    sh[tid] = m; __syncthreads();
    for (int off = 128; off > 0; off >>= 1) {
        if (tid < off) sh[tid] = fmaxf(sh[tid], sh[tid + off]);
        __syncthreads();
    }
    m = sh[0];
    __syncthreads();

    v.x = expf(v.x - m); v.y = expf(v.y - m);
    v.z = expf(v.z - m); v.w = expf(v.w - m);
    sh[tid] = v.x + v.y + v.z + v.w;
    __syncthreads();
    for (int off = 128; off > 0; off >>= 1) {
        if (tid < off) sh[tid] += sh[tid + off];
        __syncthreads();
    }
    float inv = 1.f / sh[0];
    v.x *= inv; v.y *= inv; v.z *= inv; v.w *= inv;
    p4[tid] = v;
}

// ---------------------------------------------------------------------------
extern "C" void kernel_launch(void* const* d_in, const int* in_sizes, int n_in,
                              void* d_out, int out_size)
{
    const float* x  = (const float*)d_in[0];
    const float* gs = (const float*)d_in[1];
    const float* gb = (const float*)d_in[2];
    const float* wq = (const float*)d_in[3];
    const float* bq = (const float*)d_in[4];
    const float* wk = (const float*)d_in[5];
    const float* bk = (const float*)d_in[6];
    const float* wv = (const float*)d_in[7];
    const float* bv = (const float*)d_in[8];
    const float* wp = (const float*)d_in[9];
    const float* bp = (const float*)d_in[10];
    float* out = (float*)d_out;

    float *hn, *q, *k, *v, *o, *attn;
    cudaGetSymbolAddress((void**)&hn,   g_hn);
    cudaGetSymbolAddress((void**)&q,    g_q);
    cudaGetSymbolAddress((void**)&k,    g_k);
    cudaGetSymbolAddress((void**)&v,    g_v);
    cudaGetSymbolAddress((void**)&o,    g_o);
    cudaGetSymbolAddress((void**)&attn, g_attn);

    const size_t sCH = (size_t)C_ * HW;     // 512*1024
    const size_t sAA = (size_t)HW * HW;     // 1024*1024
    const float  scl = 1.f / sqrtf((float)C_);

    // 1) GroupNorm
    gn_kernel<<<B_ * GRP, 256>>>(x, gs, gb, hn);

    // 2) q/k/v = W @ hn + b   (M=512, N=1024, K=512)
    {
        dim3 grid(HW / 128, C_ / 128, B_);
        gemm_kernel<false, false, true, false><<<grid, 256>>>(
            wq, hn, q, bq, nullptr, C_, HW, C_, 0, sCH, sCH, 0, 1.f);
        gemm_kernel<false, false, true, false><<<grid, 256>>>(
            wk, hn, k, bk, nullptr, C_, HW, C_, 0, sCH, sCH, 0, 1.f);
        gemm_kernel<false, false, true, false><<<grid, 256>>>(
            wv, hn, v, bv, nullptr, C_, HW, C_, 0, sCH, sCH, 0, 1.f);
    }

    // 3) scores S = q^T k * c^-0.5   (M=1024, N=1024, K=512) ; A stored [K,M]
    {
        dim3 grid(HW / 128, HW / 128, B_);
        gemm_kernel<true, false, false, false><<<grid, 256>>>(
            q, k, attn, nullptr, nullptr, HW, HW, C_, sCH, sCH, sAA, 0, scl);
    }

    // 4) softmax over rows
    softmax_kernel<<<B_ * HW, 256>>>(attn);

    // 5) o[c,i] = sum_j v[c,j] * attn[i,j]  (M=512, N=1024, K=1024) ; B stored [N,K]
    {
        dim3 grid(HW / 128, C_ / 128, B_);
        gemm_kernel<false, true, false, false><<<grid, 256>>>(
            v, attn, o, nullptr, nullptr, C_, HW, HW, sCH, sAA, sCH, 0, 1.f);
    }

    // 6) out = Wp @ o + bp + x  (M=512, N=1024, K=512)
    {
        dim3 grid(HW / 128, C_ / 128, B_);
        gemm_kernel<false, false, true, true><<<grid, 256>>>(
            wp, o, out, bp, x, C_, HW, C_, 0, sCH, sCH, sCH, 1.f);
    }
}

// round 3
// speedup vs baseline: 4.0163x; 4.0163x over previous
#include <cuda_runtime.h>
#include <cstdint>
#include <math.h>

#define B_  32
#define C_  512
#define HW  1024
#define EPS 1e-5f

// ---------------------------------------------------------------------------
// Scratch (__device__ globals; allocation-free rule)
// ---------------------------------------------------------------------------
__device__ __align__(128) float g_hnT[(size_t)B_ * HW * C_];   // [b, p, c]
__device__ __align__(128) float g_qT [(size_t)B_ * HW * C_];   // [b, p, c]
__device__ __align__(128) float g_kT [(size_t)B_ * HW * C_];   // [b, p, c]
__device__ __align__(128) float g_v  [(size_t)B_ * C_ * HW];   // [b, c, p]
__device__ __align__(128) float g_oT [(size_t)B_ * HW * C_];   // [b, p, c]
__device__ __align__(128) float g_attn[(size_t)B_ * HW * HW];  // [b, i, j]
__device__ float2 g_stats[B_ * 32];

// ---------------------------------------------------------------------------
// Helpers
// ---------------------------------------------------------------------------
__device__ __forceinline__ uint32_t smem_u32(const void* p) {
    uint32_t a;
    asm("{ .reg .u64 t; cvta.to.shared.u64 t, %1; cvt.u32.u64 %0, t; }" : "=r"(a) : "l"(p));
    return a;
}
__device__ __forceinline__ void cp16(uint32_t s, const void* g) {
    asm volatile("cp.async.cg.shared.global [%0], [%1], 16;" :: "r"(s), "l"(g));
}
__device__ __forceinline__ uint32_t tf32r(float f) {
    uint32_t r; asm("cvt.rna.tf32.f32 %0, %1;" : "=r"(r) : "f"(f)); return r;
}
__device__ __forceinline__ void mma8(float* d, const uint32_t* a, uint32_t b0, uint32_t b1) {
    asm volatile("mma.sync.aligned.m16n8k8.row.col.f32.tf32.tf32.f32 "
        "{%0,%1,%2,%3}, {%4,%5,%6,%7}, {%8,%9}, {%0,%1,%2,%3};"
        : "+f"(d[0]), "+f"(d[1]), "+f"(d[2]), "+f"(d[3])
        : "r"(a[0]), "r"(a[1]), "r"(a[2]), "r"(a[3]), "r"(b0), "r"(b1));
}

// ---------------------------------------------------------------------------
// GroupNorm pass 1: stats per (batch, group)
// ---------------------------------------------------------------------------
__global__ __launch_bounds__(256) void gn_stats_kernel(const float* __restrict__ x,
                                                       float2* __restrict__ stats)
{
    int b = blockIdx.x >> 5, g = blockIdx.x & 31;
    const int n = 16 * HW;
    size_t base = ((size_t)b * C_ + (size_t)g * 16) * HW;
    const float4* x4 = (const float4*)(x + base);
    float s = 0.f, ss = 0.f;
    for (int i = threadIdx.x; i < n / 4; i += 256) {
        float4 v = x4[i];
        s  += v.x + v.y + v.z + v.w;
        ss += v.x * v.x + v.y * v.y + v.z * v.z + v.w * v.w;
    }
    __shared__ float sh_s[256], sh_ss[256];
    sh_s[threadIdx.x] = s; sh_ss[threadIdx.x] = ss;
    __syncthreads();
    for (int off = 128; off > 0; off >>= 1) {
        if (threadIdx.x < off) {
            sh_s[threadIdx.x]  += sh_s[threadIdx.x + off];
            sh_ss[threadIdx.x] += sh_ss[threadIdx.x + off];
        }
        __syncthreads();
    }
    if (threadIdx.x == 0) {
        float mean = sh_s[0] * (1.f / n);
        float var  = sh_ss[0] * (1.f / n) - mean * mean;
        stats[blockIdx.x] = make_float2(mean, rsqrtf(var + EPS));
    }
}

// ---------------------------------------------------------------------------
// GroupNorm pass 2: normalize + transpose to hnT[b, p, c]
// ---------------------------------------------------------------------------
__global__ __launch_bounds__(256) void gn_transpose_kernel(
    const float* __restrict__ x, const float* __restrict__ scale,
    const float* __restrict__ bias, const float2* __restrict__ stats,
    float* __restrict__ hnT)
{
    __shared__ float tile[32][33];
    int b = blockIdx.z, c0 = blockIdx.y * 32, p0 = blockIdx.x * 32;
    int lane = threadIdx.x & 31, r = threadIdx.x >> 5;
    #pragma unroll
    for (int i = 0; i < 4; i++) {
        int cl = r + i * 8, ch = c0 + cl;
        float2 st = stats[b * 32 + (ch >> 4)];
        float a = scale[ch] * st.y;
        float ad = bias[ch] - st.x * a;
        tile[cl][lane] = x[((size_t)b * C_ + ch) * HW + p0 + lane] * a + ad;
    }
    __syncthreads();
    #pragma unroll
    for (int i = 0; i < 4; i++) {
        int pl = r + i * 8;
        hnT[((size_t)b * HW + p0 + pl) * C_ + c0 + lane] = tile[lane][pl];
    }
}

// ---------------------------------------------------------------------------
// tf32 mma.sync GEMM: D[m,n] = alpha * sum_k A[m,k]*B[n,k]  (+bias) (+R)
// A: [M,K] (k contiguous), B: [N,K] (k contiguous). Tile 128x128x16,
// 4-stage cp.async ring, warp tile 32x64 (m16n8k8).
// ---------------------------------------------------------------------------
#define BM 128
#define BN 128
#define BK 16
#define ASTRIDE 20                        // BK + 4 pad (floats)
#define STAGE_FLOATS (BM * ASTRIDE)       // 2560
#define NSTAGE 4
#define GEMM_SMEM (2 * NSTAGE * STAGE_FLOATS * 4)   // 81920 bytes

template<bool BIAS_M, bool BIAS_N, bool RES>
__global__ __launch_bounds__(256, 2) void gemm_mma(
    const float* __restrict__ A, const float* __restrict__ Bm, float* __restrict__ Cm,
    const float* __restrict__ bias, const float* __restrict__ R,
    int M, int N, int K, size_t sA, size_t sB, size_t sC, size_t sR, float alpha)
{
    extern __shared__ float smem[];
    float* As = smem;
    float* Bs = smem + NSTAGE * STAGE_FLOATS;
    uint32_t as_u = smem_u32(As);
    uint32_t bs_u = smem_u32(Bs);

    int tid = threadIdx.x, lane = tid & 31, wid = tid >> 5;
    int bz = blockIdx.z;
    A += sA * bz; Bm += sB * bz; Cm += sC * bz;
    if (RES) R += sR * bz;
    int m0 = blockIdx.y * BM, n0 = blockIdx.x * BN;

    int wm = (wid >> 1) * 32;      // warp m-offset within tile
    int wn = (wid & 1) * 64;       // warp n-offset within tile
    int g = lane >> 2, c = lane & 3;

    float acc[2][8][4];
    #pragma unroll
    for (int mt = 0; mt < 2; mt++)
        #pragma unroll
        for (int nt = 0; nt < 8; nt++)
            #pragma unroll
            for (int r_ = 0; r_ < 4; r_++) acc[mt][nt][r_] = 0.f;

    int lrow = tid >> 2, lch = tid & 3;    // loader: 128 rows x 4 x 16B per 512...
    auto load_tile = [&](int kt, int st) {
        const float* Ag = A + (size_t)m0 * K + kt * BK;
        const float* Bg = Bm + (size_t)n0 * K + kt * BK;
        uint32_t ao = (uint32_t)(st * STAGE_FLOATS) * 4u;
        #pragma unroll
        for (int i = 0; i < 2; i++) {
            int row = lrow + i * 64;
            uint32_t so = ao + (uint32_t)(row * ASTRIDE + lch * 4) * 4u;
            cp16(as_u + so, Ag + (size_t)row * K + lch * 4);
            cp16(bs_u + so, Bg + (size_t)row * K + lch * 4);
        }
        asm volatile("cp.async.commit_group;" ::: "memory");
    };

    load_tile(0, 0); load_tile(1, 1); load_tile(2, 2);

    const int KT = K / BK;
    for (int kt = 0; kt < KT; kt++) {
        asm volatile("cp.async.wait_group 2;" ::: "memory");
        __syncthreads();
        int pt = kt + 3;
        if (pt < KT) load_tile(pt, pt & 3);

        const float* Asd = As + (kt & 3) * STAGE_FLOATS + (wm) * ASTRIDE;
        const float* Bsd = Bs + (kt & 3) * STAGE_FLOATS + (wn) * ASTRIDE;
        #pragma unroll
        for (int ks = 0; ks < 2; ks++) {
            int k8 = ks * 8;
            uint32_t af[2][4];
            #pragma unroll
            for (int mt = 0; mt < 2; mt++) {
                const float* p = Asd + mt * 16 * ASTRIDE + k8;
                af[mt][0] = tf32r(p[g * ASTRIDE + c]);
                af[mt][1] = tf32r(p[(g + 8) * ASTRIDE + c]);
                af[mt][2] = tf32r(p[g * ASTRIDE + c + 4]);
                af[mt][3] = tf32r(p[(g + 8) * ASTRIDE + c + 4]);
            }
            #pragma unroll
            for (int nt = 0; nt < 8; nt++) {
                const float* p = Bsd + nt * 8 * ASTRIDE + k8;
                uint32_t b0 = tf32r(p[g * ASTRIDE + c]);
                uint32_t b1 = tf32r(p[g * ASTRIDE + c + 4]);
                mma8(acc[0][nt], af[0], b0, b1);
                mma8(acc[1][nt], af[1], b0, b1);
            }
        }
    }

    // epilogue
    #pragma unroll
    for (int mt = 0; mt < 2; mt++) {
        #pragma unroll
        for (int half = 0; half < 2; half++) {
            int m = m0 + wm + mt * 16 + g + half * 8;
            float bm = BIAS_M ? bias[m] : 0.f;
            #pragma unroll
            for (int nt = 0; nt < 8; nt++) {
                int n = n0 + wn + nt * 8 + c * 2;
                float v0 = acc[mt][nt][half * 2 + 0] * alpha + bm;
                float v1 = acc[mt][nt][half * 2 + 1] * alpha + bm;
                if (BIAS_N) { v0 += bias[n]; v1 += bias[n + 1]; }
                size_t off = (size_t)m * N + n;
                if (RES) { v0 += R[off]; v1 += R[off + 1]; }
                *(float2*)(Cm + off) = make_float2(v0, v1);
            }
        }
    }
}

// ---------------------------------------------------------------------------
// Row softmax over 1024 entries
// ---------------------------------------------------------------------------
__global__ __launch_bounds__(256) void softmax_kernel(float* __restrict__ attn)
{
    size_t row = blockIdx.x;
    float4* p4 = (float4*)(attn + row * HW);
    int tid = threadIdx.x;
    float4 v = p4[tid];
    __shared__ float sh[256];
    float m = fmaxf(fmaxf(v.x, v.y), fmaxf(v.z, v.w));
    sh[tid] = m; __syncthreads();
    for (int off = 128; off > 0; off >>= 1) {
        if (tid < off) sh[tid] = fmaxf(sh[tid], sh[tid + off]);
        __syncthreads();
    }
    m = sh[0];
    __syncthreads();
    v.x = expf(v.x - m); v.y = expf(v.y - m);
    v.z = expf(v.z - m); v.w = expf(v.w - m);
    sh[tid] = v.x + v.y + v.z + v.w;
    __syncthreads();
    for (int off = 128; off > 0; off >>= 1) {
        if (tid < off) sh[tid] += sh[tid + off];
        __syncthreads();
    }
    float inv = 1.f / sh[0];
    v.x *= inv; v.y *= inv; v.z *= inv; v.w *= inv;
    p4[tid] = v;
}

// ---------------------------------------------------------------------------
extern "C" void kernel_launch(void* const* d_in, const int* in_sizes, int n_in,
                              void* d_out, int out_size)
{
    const float* x  = (const float*)d_in[0];
    const float* gs = (const float*)d_in[1];
    const float* gb = (const float*)d_in[2];
    const float* wq = (const float*)d_in[3];
    const float* bq = (const float*)d_in[4];
    const float* wk = (const float*)d_in[5];
    const float* bk = (const float*)d_in[6];
    const float* wv = (const float*)d_in[7];
    const float* bv = (const float*)d_in[8];
    const float* wp = (const float*)d_in[9];
    const float* bp = (const float*)d_in[10];
    float* out = (float*)d_out;

    float *hnT, *qT, *kT, *v, *oT, *attn; float2* stats;
    cudaGetSymbolAddress((void**)&hnT,  g_hnT);
    cudaGetSymbolAddress((void**)&qT,   g_qT);
    cudaGetSymbolAddress((void**)&kT,   g_kT);
    cudaGetSymbolAddress((void**)&v,    g_v);
    cudaGetSymbolAddress((void**)&oT,   g_oT);
    cudaGetSymbolAddress((void**)&attn, g_attn);
    cudaGetSymbolAddress((void**)&stats, g_stats);

    cudaFuncSetAttribute(gemm_mma<false, true,  false>, cudaFuncAttributeMaxDynamicSharedMemorySize, GEMM_SMEM);
    cudaFuncSetAttribute(gemm_mma<true,  false, false>, cudaFuncAttributeMaxDynamicSharedMemorySize, GEMM_SMEM);
    cudaFuncSetAttribute(gemm_mma<false, false, false>, cudaFuncAttributeMaxDynamicSharedMemorySize, GEMM_SMEM);
    cudaFuncSetAttribute(gemm_mma<true,  false, true >, cudaFuncAttributeMaxDynamicSharedMemorySize, GEMM_SMEM);

    const size_t sCH = (size_t)C_ * HW;
    const size_t sAA = (size_t)HW * HW;
    const float  scl = 1.f / sqrtf((float)C_);

    // 1) GroupNorm stats + normalize/transpose -> hnT[b,p,c]
    gn_stats_kernel<<<B_ * 32, 256>>>(x, stats);
    gn_transpose_kernel<<<dim3(HW / 32, C_ / 32, B_), 256>>>(x, gs, gb, stats, hnT);

    // 2) QT/KT[p,co] = sum_c hnT[p,c]*w[co,c] + b[co]   (M=1024,N=512,K=512)
    {
        dim3 g(512 / BN, 1024 / BM, B_);
        gemm_mma<false, true, false><<<g, 256, GEMM_SMEM>>>(
            hnT, wq, qT, bq, nullptr, 1024, 512, 512, sCH, 0, sCH, 0, 1.f);
        gemm_mma<false, true, false><<<g, 256, GEMM_SMEM>>>(
            hnT, wk, kT, bk, nullptr, 1024, 512, 512, sCH, 0, sCH, 0, 1.f);
    }
    // 3) V[co,p] = sum_c wv[co,c]*hnT[p,c] + bv[co]    (M=512,N=1024,K=512)
    {
        dim3 g(1024 / BN, 512 / BM, B_);
        gemm_mma<true, false, false><<<g, 256, GEMM_SMEM>>>(
            wv, hnT, v, bv, nullptr, 512, 1024, 512, 0, sCH, sCH, 0, 1.f);
    }
    // 4) S[i,j] = scl * sum_c QT[i,c]*KT[j,c]          (M=1024,N=1024,K=512)
    {
        dim3 g(1024 / BN, 1024 / BM, B_);
        gemm_mma<false, false, false><<<g, 256, GEMM_SMEM>>>(
            qT, kT, attn, nullptr, nullptr, 1024, 1024, 512, sCH, sCH, sAA, 0, scl);
    }
    // 5) softmax rows
    softmax_kernel<<<B_ * HW, 256>>>(attn);

    // 6) OT[i,co] = sum_j attn[i,j]*V[co,j]            (M=1024,N=512,K=1024)
    {
        dim3 g(512 / BN, 1024 / BM, B_);
        gemm_mma<false, false, false><<<g, 256, GEMM_SMEM>>>(
            attn, v, oT, nullptr, nullptr, 1024, 512, 1024, sAA, sCH, sCH, 0, 1.f);
    }
    // 7) out[co,p] = sum_c wp[co,c]*OT[p,c] + bp[co] + x[co,p]  (M=512,N=1024,K=512)
    {
        dim3 g(1024 / BN, 512 / BM, B_);
        gemm_mma<true, false, true><<<g, 256, GEMM_SMEM>>>(
            wp, oT, out, bp, x, 512, 1024, 512, 0, sCH, sCH, sCH, 1.f);
    }
}

// round 4
// speedup vs baseline: 8.0632x; 2.0076x over previous
#include <cuda_runtime.h>
#include <cuda_bf16.h>
#include <cstdint>
#include <math.h>

#define B_  32
#define C_  512
#define HW  1024
#define EPS 1e-5f

typedef __nv_bfloat16 bf16;

// ---------------------------------------------------------------------------
// Scratch (__device__ globals; allocation-free rule)
// ---------------------------------------------------------------------------
__device__ __align__(128) bf16  g_hnT[(size_t)B_ * HW * C_];   // [b, p, c]
__device__ __align__(128) bf16  g_qT [(size_t)B_ * HW * C_];   // [b, p, c]
__device__ __align__(128) bf16  g_kT [(size_t)B_ * HW * C_];   // [b, p, c]
__device__ __align__(128) bf16  g_v  [(size_t)B_ * C_ * HW];   // [b, c, p]
__device__ __align__(128) bf16  g_oT [(size_t)B_ * HW * C_];   // [b, p, c]
__device__ __align__(128) float g_attn [(size_t)B_ * HW * HW]; // fp32 scores
__device__ __align__(128) bf16  g_probs[(size_t)B_ * HW * HW]; // bf16 probs
__device__ __align__(128) bf16  g_w[4][C_ * C_];               // wq,wk,wv,wp bf16
__device__ float2 g_stats[B_ * 32];

// ---------------------------------------------------------------------------
// Helpers
// ---------------------------------------------------------------------------
__device__ __forceinline__ uint32_t smem_u32(const void* p) {
    uint32_t a;
    asm("{ .reg .u64 t; cvta.to.shared.u64 t, %1; cvt.u32.u64 %0, t; }" : "=r"(a) : "l"(p));
    return a;
}
__device__ __forceinline__ void cp16(uint32_t s, const void* g) {
    asm volatile("cp.async.cg.shared.global [%0], [%1], 16;" :: "r"(s), "l"(g));
}
__device__ __forceinline__ void ldsm4(uint32_t* r, uint32_t a) {
    asm volatile("ldmatrix.sync.aligned.m8n8.x4.shared.b16 {%0,%1,%2,%3}, [%4];"
                 : "=r"(r[0]), "=r"(r[1]), "=r"(r[2]), "=r"(r[3]) : "r"(a));
}
__device__ __forceinline__ void mma16(float* d, const uint32_t* a, uint32_t b0, uint32_t b1) {
    asm volatile("mma.sync.aligned.m16n8k16.row.col.f32.bf16.bf16.f32 "
        "{%0,%1,%2,%3}, {%4,%5,%6,%7}, {%8,%9}, {%0,%1,%2,%3};"
        : "+f"(d[0]), "+f"(d[1]), "+f"(d[2]), "+f"(d[3])
        : "r"(a[0]), "r"(a[1]), "r"(a[2]), "r"(a[3]), "r"(b0), "r"(b1));
}

// ---------------------------------------------------------------------------
// Weight fp32 -> bf16 conversion
// ---------------------------------------------------------------------------
__global__ __launch_bounds__(256) void cvt_kernel(const float* __restrict__ src,
                                                  bf16* __restrict__ dst, int n)
{
    int i = blockIdx.x * 256 + threadIdx.x;
    if (i * 4 < n) {
        float4 v = *(const float4*)(src + i * 4);
        __nv_bfloat162* d2 = (__nv_bfloat162*)(dst + i * 4);
        d2[0] = __floats2bfloat162_rn(v.x, v.y);
        d2[1] = __floats2bfloat162_rn(v.z, v.w);
    }
}

// ---------------------------------------------------------------------------
// GroupNorm pass 1: stats per (batch, group)
// ---------------------------------------------------------------------------
__global__ __launch_bounds__(256) void gn_stats_kernel(const float* __restrict__ x,
                                                       float2* __restrict__ stats)
{
    int b = blockIdx.x >> 5, g = blockIdx.x & 31;
    const int n = 16 * HW;
    size_t base = ((size_t)b * C_ + (size_t)g * 16) * HW;
    const float4* x4 = (const float4*)(x + base);
    float s = 0.f, ss = 0.f;
    for (int i = threadIdx.x; i < n / 4; i += 256) {
        float4 v = x4[i];
        s  += v.x + v.y + v.z + v.w;
        ss += v.x * v.x + v.y * v.y + v.z * v.z + v.w * v.w;
    }
    __shared__ float sh_s[256], sh_ss[256];
    sh_s[threadIdx.x] = s; sh_ss[threadIdx.x] = ss;
    __syncthreads();
    for (int off = 128; off > 0; off >>= 1) {
        if (threadIdx.x < off) {
            sh_s[threadIdx.x]  += sh_s[threadIdx.x + off];
            sh_ss[threadIdx.x] += sh_ss[threadIdx.x + off];
        }
        __syncthreads();
    }
    if (threadIdx.x == 0) {
        float mean = sh_s[0] * (1.f / n);
        float var  = sh_ss[0] * (1.f / n) - mean * mean;
        stats[blockIdx.x] = make_float2(mean, rsqrtf(var + EPS));
    }
}

// ---------------------------------------------------------------------------
// GroupNorm pass 2: normalize + transpose -> hnT[b, p, c] (bf16)
// ---------------------------------------------------------------------------
__global__ __launch_bounds__(256) void gn_transpose_kernel(
    const float* __restrict__ x, const float* __restrict__ scale,
    const float* __restrict__ bias, const float2* __restrict__ stats,
    bf16* __restrict__ hnT)
{
    __shared__ float tile[32][33];
    int b = blockIdx.z, c0 = blockIdx.y * 32, p0 = blockIdx.x * 32;
    int lane = threadIdx.x & 31, r = threadIdx.x >> 5;
    #pragma unroll
    for (int i = 0; i < 4; i++) {
        int cl = r + i * 8, ch = c0 + cl;
        float2 st = stats[b * 32 + (ch >> 4)];
        float a = scale[ch] * st.y;
        float ad = bias[ch] - st.x * a;
        tile[cl][lane] = x[((size_t)b * C_ + ch) * HW + p0 + lane] * a + ad;
    }
    __syncthreads();
    #pragma unroll
    for (int i = 0; i < 4; i++) {
        int pl = r + i * 8;
        hnT[((size_t)b * HW + p0 + pl) * C_ + c0 + lane] = __float2bfloat16(tile[lane][pl]);
    }
}

// ---------------------------------------------------------------------------
// bf16 mma.sync GEMM: D[m,n] = alpha * sum_k A[m,k]*B[n,k]  (+bias) (+R)
// A: [M,K] bf16 (k contig), B: [N,K] bf16 (k contig). Tile 128x128x32,
// 4-stage cp.async ring, ldmatrix fragments, warp tile 32x64 (m16n8k16).
// ---------------------------------------------------------------------------
#define BM 128
#define BN 128
#define BKB 32                         // k per tile (bf16 elems)
#define ROWB 80                        // bytes per smem row (64 data + 16 pad)
#define STAGE_B (BM * ROWB)            // 10240 bytes per operand stage
#define NSTAGE 4
#define GEMM_SMEM (2 * NSTAGE * STAGE_B)   // 81920 bytes

template<bool BIAS_M, bool BIAS_N, bool RES, bool OUTBF>
__global__ __launch_bounds__(256, 2) void gemm_bf(
    const bf16* __restrict__ A, const bf16* __restrict__ Bm, void* __restrict__ Cp,
    const float* __restrict__ bias, const float* __restrict__ R,
    int M, int N, int K, size_t sA, size_t sB, size_t sC, size_t sR, float alpha)
{
    extern __shared__ char smem[];
    uint32_t su = smem_u32(smem);
    const uint32_t BOFF = NSTAGE * STAGE_B;

    int tid = threadIdx.x, lane = tid & 31, wid = tid >> 5;
    int bz = blockIdx.z;
    A += sA * bz; Bm += sB * bz;
    if (RES) R += sR * bz;
    int m0 = blockIdx.y * BM, n0 = blockIdx.x * BN;

    int wm = (wid >> 1) * 32;
    int wn = (wid & 1) * 64;
    int g = lane >> 2, c = lane & 3;

    // ldmatrix per-lane offsets (bytes, within a stage)
    int a_row = (lane & 7) + ((lane >> 3) & 1) * 8;
    int a_kh  = lane >> 4;
    uint32_t aoff0 = (uint32_t)((wm + a_row) * ROWB + a_kh * 16);
    uint32_t aoff1 = aoff0 + 16 * ROWB;
    int b_row = (lane & 7) + ((lane >> 4) & 1) * 8;
    int b_kh  = (lane >> 3) & 1;
    uint32_t boffb = (uint32_t)((wn + b_row) * ROWB + b_kh * 16);

    float acc[2][8][4];
    #pragma unroll
    for (int mt = 0; mt < 2; mt++)
        #pragma unroll
        for (int nt = 0; nt < 8; nt++)
            #pragma unroll
            for (int r_ = 0; r_ < 4; r_++) acc[mt][nt][r_] = 0.f;

    int lrow = tid >> 2, lch = tid & 3;
    auto load_tile = [&](int kt, int st) {
        const bf16* Ag = A  + (size_t)m0 * K + kt * BKB;
        const bf16* Bg = Bm + (size_t)n0 * K + kt * BKB;
        uint32_t so = su + (uint32_t)st * STAGE_B;
        #pragma unroll
        for (int i = 0; i < 2; i++) {
            int row = lrow + i * 64;
            uint32_t off = (uint32_t)(row * ROWB + lch * 16);
            cp16(so + off,        Ag + (size_t)row * K + lch * 8);
            cp16(so + BOFF + off, Bg + (size_t)row * K + lch * 8);
        }
        asm volatile("cp.async.commit_group;" ::: "memory");
    };

    load_tile(0, 0); load_tile(1, 1); load_tile(2, 2);

    const int KT = K / BKB;
    for (int kt = 0; kt < KT; kt++) {
        asm volatile("cp.async.wait_group 2;" ::: "memory");
        __syncthreads();
        int pt = kt + 3;
        if (pt < KT) load_tile(pt, pt & 3);

        uint32_t abase = su + (uint32_t)(kt & 3) * STAGE_B;
        uint32_t bbase = abase + BOFF;
        #pragma unroll
        for (int sl = 0; sl < 2; sl++) {
            uint32_t ko = sl * 32;
            uint32_t af[2][4];
            ldsm4(af[0], abase + aoff0 + ko);
            ldsm4(af[1], abase + aoff1 + ko);
            #pragma unroll
            for (int pr = 0; pr < 4; pr++) {
                uint32_t bf_[4];
                ldsm4(bf_, bbase + boffb + pr * (16 * ROWB) + ko);
                mma16(acc[0][pr * 2 + 0], af[0], bf_[0], bf_[1]);
                mma16(acc[1][pr * 2 + 0], af[1], bf_[0], bf_[1]);
                mma16(acc[0][pr * 2 + 1], af[0], bf_[2], bf_[3]);
                mma16(acc[1][pr * 2 + 1], af[1], bf_[2], bf_[3]);
            }
        }
    }

    // epilogue
    #pragma unroll
    for (int mt = 0; mt < 2; mt++) {
        #pragma unroll
        for (int half = 0; half < 2; half++) {
            int m = m0 + wm + mt * 16 + g + half * 8;
            float bm = BIAS_M ? bias[m] : 0.f;
            #pragma unroll
            for (int nt = 0; nt < 8; nt++) {
                int n = n0 + wn + nt * 8 + c * 2;
                float v0 = acc[mt][nt][half * 2 + 0] * alpha + bm;
                float v1 = acc[mt][nt][half * 2 + 1] * alpha + bm;
                if (BIAS_N) { v0 += bias[n]; v1 += bias[n + 1]; }
                size_t off = (size_t)m * N + n;
                if (RES) { v0 += R[off]; v1 += R[off + 1]; }
                if (OUTBF) {
                    *(__nv_bfloat162*)((bf16*)Cp + sC * bz + off) = __floats2bfloat162_rn(v0, v1);
                } else {
                    *(float2*)((float*)Cp + sC * bz + off) = make_float2(v0, v1);
                }
            }
        }
    }
}

// ---------------------------------------------------------------------------
// Row softmax: fp32 scores in -> bf16 probs out
// ---------------------------------------------------------------------------
__global__ __launch_bounds__(256) void softmax_kernel(const float* __restrict__ attn,
                                                      bf16* __restrict__ probs)
{
    size_t row = blockIdx.x;
    const float4* p4 = (const float4*)(attn + row * HW);
    int tid = threadIdx.x;
    float4 v = p4[tid];
    __shared__ float sh[256];
    float m = fmaxf(fmaxf(v.x, v.y), fmaxf(v.z, v.w));
    sh[tid] = m; __syncthreads();
    for (int off = 128; off > 0; off >>= 1) {
        if (tid < off) sh[tid] = fmaxf(sh[tid], sh[tid + off]);
        __syncthreads();
    }
    m = sh[0];
    __syncthreads();
    v.x = expf(v.x - m); v.y = expf(v.y - m);
    v.z = expf(v.z - m); v.w = expf(v.w - m);
    sh[tid] = v.x + v.y + v.z + v.w;
    __syncthreads();
    for (int off = 128; off > 0; off >>= 1) {
        if (tid < off) sh[tid] += sh[tid + off];
        __syncthreads();
    }
    float inv = 1.f / sh[0];
    __nv_bfloat162* o2 = (__nv_bfloat162*)(probs + row * HW) + tid * 2;
    o2[0] = __floats2bfloat162_rn(v.x * inv, v.y * inv);
    o2[1] = __floats2bfloat162_rn(v.z * inv, v.w * inv);
}

// ---------------------------------------------------------------------------
extern "C" void kernel_launch(void* const* d_in, const int* in_sizes, int n_in,
                              void* d_out, int out_size)
{
    const float* x  = (const float*)d_in[0];
    const float* gs = (const float*)d_in[1];
    const float* gb = (const float*)d_in[2];
    const float* wq = (const float*)d_in[3];
    const float* bq = (const float*)d_in[4];
    const float* wk = (const float*)d_in[5];
    const float* bk = (const float*)d_in[6];
    const float* wv = (const float*)d_in[7];
    const float* bv = (const float*)d_in[8];
    const float* wp = (const float*)d_in[9];
    const float* bp = (const float*)d_in[10];
    float* out = (float*)d_out;

    bf16 *hnT, *qT, *kT, *v, *oT, *probs, *wb; float* attn; float2* stats;
    cudaGetSymbolAddress((void**)&hnT,   g_hnT);
    cudaGetSymbolAddress((void**)&qT,    g_qT);
    cudaGetSymbolAddress((void**)&kT,    g_kT);
    cudaGetSymbolAddress((void**)&v,     g_v);
    cudaGetSymbolAddress((void**)&oT,    g_oT);
    cudaGetSymbolAddress((void**)&attn,  g_attn);
    cudaGetSymbolAddress((void**)&probs, g_probs);
    cudaGetSymbolAddress((void**)&wb,    g_w);
    cudaGetSymbolAddress((void**)&stats, g_stats);
    bf16 *wqb = wb, *wkb = wb + C_ * C_, *wvb = wb + 2 * C_ * C_, *wpb = wb + 3 * C_ * C_;

    cudaFuncSetAttribute(gemm_bf<false, true,  false, true >, cudaFuncAttributeMaxDynamicSharedMemorySize, GEMM_SMEM);
    cudaFuncSetAttribute(gemm_bf<true,  false, false, true >, cudaFuncAttributeMaxDynamicSharedMemorySize, GEMM_SMEM);
    cudaFuncSetAttribute(gemm_bf<false, false, false, false>, cudaFuncAttributeMaxDynamicSharedMemorySize, GEMM_SMEM);
    cudaFuncSetAttribute(gemm_bf<false, false, false, true >, cudaFuncAttributeMaxDynamicSharedMemorySize, GEMM_SMEM);
    cudaFuncSetAttribute(gemm_bf<true,  false, true,  false>, cudaFuncAttributeMaxDynamicSharedMemorySize, GEMM_SMEM);

    const size_t sCH = (size_t)C_ * HW;
    const size_t sAA = (size_t)HW * HW;
    const float  scl = 1.f / sqrtf((float)C_);
    const int    WN  = C_ * C_;

    // 0) weights -> bf16
    cvt_kernel<<<WN / 1024, 256>>>(wq, wqb, WN);
    cvt_kernel<<<WN / 1024, 256>>>(wk, wkb, WN);
    cvt_kernel<<<WN / 1024, 256>>>(wv, wvb, WN);
    cvt_kernel<<<WN / 1024, 256>>>(wp, wpb, WN);

    // 1) GroupNorm stats + normalize/transpose -> hnT (bf16)
    gn_stats_kernel<<<B_ * 32, 256>>>(x, stats);
    gn_transpose_kernel<<<dim3(HW / 32, C_ / 32, B_), 256>>>(x, gs, gb, stats, hnT);

    // 2) QT/KT[p,o] = hnT @ w^T + b        (M=1024, N=512, K=512) -> bf16
    {
        dim3 g(512 / BN, 1024 / BM, B_);
        gemm_bf<false, true, false, true><<<g, 256, GEMM_SMEM>>>(
            hnT, wqb, qT, bq, nullptr, 1024, 512, 512, sCH, 0, sCH, 0, 1.f);
        gemm_bf<false, true, false, true><<<g, 256, GEMM_SMEM>>>(
            hnT, wkb, kT, bk, nullptr, 1024, 512, 512, sCH, 0, sCH, 0, 1.f);
    }
    // 3) V[co,p] = wv @ hnT^T + bv         (M=512, N=1024, K=512) -> bf16
    {
        dim3 g(1024 / BN, 512 / BM, B_);
        gemm_bf<true, false, false, true><<<g, 256, GEMM_SMEM>>>(
            wvb, hnT, v, bv, nullptr, 512, 1024, 512, 0, sCH, sCH, 0, 1.f);
    }
    // 4) S = scl * QT @ KT^T               (M=1024, N=1024, K=512) -> fp32
    {
        dim3 g(1024 / BN, 1024 / BM, B_);
        gemm_bf<false, false, false, false><<<g, 256, GEMM_SMEM>>>(
            qT, kT, attn, nullptr, nullptr, 1024, 1024, 512, sCH, sCH, sAA, 0, scl);
    }
    // 5) softmax -> bf16 probs
    softmax_kernel<<<B_ * HW, 256>>>(attn, probs);

    // 6) OT[i,co] = probs @ V^T            (M=1024, N=512, K=1024) -> bf16
    {
        dim3 g(512 / BN, 1024 / BM, B_);
        gemm_bf<false, false, false, true><<<g, 256, GEMM_SMEM>>>(
            probs, v, oT, nullptr, nullptr, 1024, 512, 1024, sAA, sCH, sCH, 0, 1.f);
    }
    // 7) out[co,p] = wp @ OT^T + bp + x    (M=512, N=1024, K=512) -> fp32 + residual
    {
        dim3 g(1024 / BN, 512 / BM, B_);
        gemm_bf<true, false, true, false><<<g, 256, GEMM_SMEM>>>(
            wpb, oT, out, bp, x, 512, 1024, 512, 0, sCH, sCH, sCH, 1.f);
    }
}

// round 5
// speedup vs baseline: 8.3498x; 1.0355x over previous
#include <cuda_runtime.h>
#include <cuda_bf16.h>
#include <cstdint>
#include <math.h>

#define B_  32
#define C_  512
#define HW  1024
#define EPS 1e-5f

typedef __nv_bfloat16 bf16;

// ---------------------------------------------------------------------------
// Scratch (__device__ globals; allocation-free rule)
// ---------------------------------------------------------------------------
__device__ __align__(128) bf16  g_hnT[(size_t)B_ * HW * C_];   // [b, p, c]
__device__ __align__(128) bf16  g_qT [(size_t)B_ * HW * C_];   // [b, p, c]
__device__ __align__(128) bf16  g_kT [(size_t)B_ * HW * C_];   // [b, p, c]
__device__ __align__(128) bf16  g_v  [(size_t)B_ * C_ * HW];   // [b, c, p]
__device__ __align__(128) bf16  g_oT [(size_t)B_ * HW * C_];   // [b, p, c]
__device__ __align__(128) float g_attn [(size_t)B_ * HW * HW]; // fp32 scores
__device__ __align__(128) bf16  g_probs[(size_t)B_ * HW * HW]; // bf16 probs
__device__ __align__(128) bf16  g_w[4][C_ * C_];               // wq,wk,wv,wp bf16
__device__ float2 g_stats[B_ * 32];

// ---------------------------------------------------------------------------
// Helpers
// ---------------------------------------------------------------------------
__device__ __forceinline__ uint32_t smem_u32(const void* p) {
    uint32_t a;
    asm("{ .reg .u64 t; cvta.to.shared.u64 t, %1; cvt.u32.u64 %0, t; }" : "=r"(a) : "l"(p));
    return a;
}
__device__ __forceinline__ void cp16(uint32_t s, const void* g) {
    asm volatile("cp.async.cg.shared.global [%0], [%1], 16;" :: "r"(s), "l"(g));
}
__device__ __forceinline__ void ldsm4(uint32_t* r, uint32_t a) {
    asm volatile("ldmatrix.sync.aligned.m8n8.x4.shared.b16 {%0,%1,%2,%3}, [%4];"
                 : "=r"(r[0]), "=r"(r[1]), "=r"(r[2]), "=r"(r[3]) : "r"(a));
}
__device__ __forceinline__ void mma16(float* d, const uint32_t* a, uint32_t b0, uint32_t b1) {
    asm volatile("mma.sync.aligned.m16n8k16.row.col.f32.bf16.bf16.f32 "
        "{%0,%1,%2,%3}, {%4,%5,%6,%7}, {%8,%9}, {%0,%1,%2,%3};"
        : "+f"(d[0]), "+f"(d[1]), "+f"(d[2]), "+f"(d[3])
        : "r"(a[0]), "r"(a[1]), "r"(a[2]), "r"(a[3]), "r"(b0), "r"(b1));
}

// ---------------------------------------------------------------------------
// Weight fp32 -> bf16 conversion, all four weights in one launch
// ---------------------------------------------------------------------------
__global__ __launch_bounds__(256) void cvt4_kernel(
    const float* __restrict__ w0, const float* __restrict__ w1,
    const float* __restrict__ w2, const float* __restrict__ w3,
    bf16* __restrict__ dst)
{
    const float* src = (blockIdx.y == 0) ? w0 : (blockIdx.y == 1) ? w1
                     : (blockIdx.y == 2) ? w2 : w3;
    bf16* d = dst + (size_t)blockIdx.y * C_ * C_;
    int i = blockIdx.x * 256 + threadIdx.x;
    float4 v = *(const float4*)(src + i * 4);
    __nv_bfloat162* d2 = (__nv_bfloat162*)(d + i * 4);
    d2[0] = __floats2bfloat162_rn(v.x, v.y);
    d2[1] = __floats2bfloat162_rn(v.z, v.w);
}

// ---------------------------------------------------------------------------
// GroupNorm pass 1: stats per (batch, group)
// ---------------------------------------------------------------------------
__global__ __launch_bounds__(256) void gn_stats_kernel(const float* __restrict__ x,
                                                       float2* __restrict__ stats)
{
    int b = blockIdx.x >> 5, g = blockIdx.x & 31;
    const int n = 16 * HW;
    size_t base = ((size_t)b * C_ + (size_t)g * 16) * HW;
    const float4* x4 = (const float4*)(x + base);
    float s = 0.f, ss = 0.f;
    for (int i = threadIdx.x; i < n / 4; i += 256) {
        float4 v = x4[i];
        s  += v.x + v.y + v.z + v.w;
        ss += v.x * v.x + v.y * v.y + v.z * v.z + v.w * v.w;
    }
    __shared__ float sh_s[256], sh_ss[256];
    sh_s[threadIdx.x] = s; sh_ss[threadIdx.x] = ss;
    __syncthreads();
    for (int off = 128; off > 0; off >>= 1) {
        if (threadIdx.x < off) {
            sh_s[threadIdx.x]  += sh_s[threadIdx.x + off];
            sh_ss[threadIdx.x] += sh_ss[threadIdx.x + off];
        }
        __syncthreads();
    }
    if (threadIdx.x == 0) {
        float mean = sh_s[0] * (1.f / n);
        float var  = sh_ss[0] * (1.f / n) - mean * mean;
        stats[blockIdx.x] = make_float2(mean, rsqrtf(var + EPS));
    }
}

// ---------------------------------------------------------------------------
// GroupNorm pass 2: normalize + transpose -> hnT[b, p, c] (bf16)
// ---------------------------------------------------------------------------
__global__ __launch_bounds__(256) void gn_transpose_kernel(
    const float* __restrict__ x, const float* __restrict__ scale,
    const float* __restrict__ bias, const float2* __restrict__ stats,
    bf16* __restrict__ hnT)
{
    __shared__ float tile[32][33];
    int b = blockIdx.z, c0 = blockIdx.y * 32, p0 = blockIdx.x * 32;
    int lane = threadIdx.x & 31, r = threadIdx.x >> 5;
    #pragma unroll
    for (int i = 0; i < 4; i++) {
        int cl = r + i * 8, ch = c0 + cl;
        float2 st = stats[b * 32 + (ch >> 4)];
        float a = scale[ch] * st.y;
        float ad = bias[ch] - st.x * a;
        tile[cl][lane] = x[((size_t)b * C_ + ch) * HW + p0 + lane] * a + ad;
    }
    __syncthreads();
    #pragma unroll
    for (int i = 0; i < 4; i++) {
        int pl = r + i * 8;
        hnT[((size_t)b * HW + p0 + pl) * C_ + c0 + lane] = __float2bfloat16(tile[lane][pl]);
    }
}

// ---------------------------------------------------------------------------
// bf16 mma.sync GEMM: D[m,n] = alpha * sum_k A[m,k]*B[n,k]  (+bias) (+R)
// A: [M,K] bf16 (k contig), B: [N,K] bf16 (k contig). CTA tile 128x128x32,
// 128 threads (4 warps, 2x2), warp tile 64x64, 4-stage cp.async ring.
// ---------------------------------------------------------------------------
#define BM 128
#define BN 128
#define BKB 32                         // k per tile (bf16 elems)
#define ROWB 80                        // bytes per smem row (64 data + 16 pad)
#define STAGE_B (BM * ROWB)            // 10240 bytes per operand stage
#define NSTAGE 4
#define GEMM_SMEM (2 * NSTAGE * STAGE_B)   // 81920 bytes

template<bool BIAS_M, bool BIAS_N, bool RES, bool OUTBF>
__global__ __launch_bounds__(128, 2) void gemm_bf(
    const bf16* __restrict__ A, const bf16* __restrict__ Bm, void* __restrict__ Cp,
    const float* __restrict__ bias, const float* __restrict__ R,
    int M, int N, int K, size_t sA, size_t sB, size_t sC, size_t sR, float alpha)
{
    extern __shared__ char smem[];
    uint32_t su = smem_u32(smem);
    const uint32_t BOFF = NSTAGE * STAGE_B;

    int tid = threadIdx.x, lane = tid & 31, wid = tid >> 5;
    int bz = blockIdx.z;
    A += sA * bz; Bm += sB * bz;
    if (RES) R += sR * bz;
    int m0 = blockIdx.y * BM, n0 = blockIdx.x * BN;

    int wm = (wid & 1) * 64;           // warp m-offset (64-wide)
    int wn = (wid >> 1) * 64;          // warp n-offset (64-wide)
    int g = lane >> 2, c = lane & 3;

    // ldmatrix per-lane offsets (bytes, within a stage)
    int a_row = (lane & 7) + ((lane >> 3) & 1) * 8;
    int a_kh  = lane >> 4;
    uint32_t aoff = (uint32_t)((wm + a_row) * ROWB + a_kh * 16);
    int b_row = (lane & 7) + ((lane >> 4) & 1) * 8;
    int b_kh  = (lane >> 3) & 1;
    uint32_t boffb = (uint32_t)((wn + b_row) * ROWB + b_kh * 16);

    float acc[4][8][4];
    #pragma unroll
    for (int mt = 0; mt < 4; mt++)
        #pragma unroll
        for (int nt = 0; nt < 8; nt++)
            #pragma unroll
            for (int r_ = 0; r_ < 4; r_++) acc[mt][nt][r_] = 0.f;

    int lrow = tid >> 2, lch = tid & 3;        // 32 rows per pass, 4 chunks
    auto load_tile = [&](int kt, int st) {
        const bf16* Ag = A  + (size_t)m0 * K + kt * BKB;
        const bf16* Bg = Bm + (size_t)n0 * K + kt * BKB;
        uint32_t so = su + (uint32_t)st * STAGE_B;
        #pragma unroll
        for (int i = 0; i < 4; i++) {
            int row = lrow + i * 32;
            uint32_t off = (uint32_t)(row * ROWB + lch * 16);
            cp16(so + off,        Ag + (size_t)row * K + lch * 8);
            cp16(so + BOFF + off, Bg + (size_t)row * K + lch * 8);
        }
        asm volatile("cp.async.commit_group;" ::: "memory");
    };

    load_tile(0, 0); load_tile(1, 1); load_tile(2, 2);

    const int KT = K / BKB;
    for (int kt = 0; kt < KT; kt++) {
        asm volatile("cp.async.wait_group 2;" ::: "memory");
        __syncthreads();
        int pt = kt + 3;
        if (pt < KT) load_tile(pt, pt & 3);

        uint32_t abase = su + (uint32_t)(kt & 3) * STAGE_B;
        uint32_t bbase = abase + BOFF;
        #pragma unroll
        for (int sl = 0; sl < 2; sl++) {
            uint32_t ko = sl * 32;
            uint32_t af[4][4];
            #pragma unroll
            for (int mt = 0; mt < 4; mt++)
                ldsm4(af[mt], abase + aoff + mt * (16 * ROWB) + ko);
            #pragma unroll
            for (int pr = 0; pr < 4; pr++) {
                uint32_t bf_[4];
                ldsm4(bf_, bbase + boffb + pr * (16 * ROWB) + ko);
                #pragma unroll
                for (int mt = 0; mt < 4; mt++) {
                    mma16(acc[mt][pr * 2 + 0], af[mt], bf_[0], bf_[1]);
                    mma16(acc[mt][pr * 2 + 1], af[mt], bf_[2], bf_[3]);
                }
            }
        }
    }

    // epilogue
    #pragma unroll
    for (int mt = 0; mt < 4; mt++) {
        #pragma unroll
        for (int half = 0; half < 2; half++) {
            int m = m0 + wm + mt * 16 + g + half * 8;
            float bm = BIAS_M ? bias[m] : 0.f;
            #pragma unroll
            for (int nt = 0; nt < 8; nt++) {
                int n = n0 + wn + nt * 8 + c * 2;
                float v0 = acc[mt][nt][half * 2 + 0] * alpha + bm;
                float v1 = acc[mt][nt][half * 2 + 1] * alpha + bm;
                if (BIAS_N) { v0 += bias[n]; v1 += bias[n + 1]; }
                size_t off = (size_t)m * N + n;
                if (RES) { v0 += R[off]; v1 += R[off + 1]; }
                if (OUTBF) {
                    *(__nv_bfloat162*)((bf16*)Cp + sC * bz + off) = __floats2bfloat162_rn(v0, v1);
                } else {
                    *(float2*)((float*)Cp + sC * bz + off) = make_float2(v0, v1);
                }
            }
        }
    }
}

// ---------------------------------------------------------------------------
// Row softmax: fp32 scores in -> bf16 probs out
// ---------------------------------------------------------------------------
__global__ __launch_bounds__(256) void softmax_kernel(const float* __restrict__ attn,
                                                      bf16* __restrict__ probs)
{
    size_t row = blockIdx.x;
    const float4* p4 = (const float4*)(attn + row * HW);
    int tid = threadIdx.x;
    float4 v = p4[tid];
    __shared__ float sh[256];
    float m = fmaxf(fmaxf(v.x, v.y), fmaxf(v.z, v.w));
    sh[tid] = m; __syncthreads();
    for (int off = 128; off > 0; off >>= 1) {
        if (tid < off) sh[tid] = fmaxf(sh[tid], sh[tid + off]);
        __syncthreads();
    }
    m = sh[0];
    __syncthreads();
    v.x = expf(v.x - m); v.y = expf(v.y - m);
    v.z = expf(v.z - m); v.w = expf(v.w - m);
    sh[tid] = v.x + v.y + v.z + v.w;
    __syncthreads();
    for (int off = 128; off > 0; off >>= 1) {
        if (tid < off) sh[tid] += sh[tid + off];
        __syncthreads();
    }
    float inv = 1.f / sh[0];
    __nv_bfloat162* o2 = (__nv_bfloat162*)(probs + row * HW) + tid * 2;
    o2[0] = __floats2bfloat162_rn(v.x * inv, v.y * inv);
    o2[1] = __floats2bfloat162_rn(v.z * inv, v.w * inv);
}

// ---------------------------------------------------------------------------
extern "C" void kernel_launch(void* const* d_in, const int* in_sizes, int n_in,
                              void* d_out, int out_size)
{
    const float* x  = (const float*)d_in[0];
    const float* gs = (const float*)d_in[1];
    const float* gb = (const float*)d_in[2];
    const float* wq = (const float*)d_in[3];
    const float* bq = (const float*)d_in[4];
    const float* wk = (const float*)d_in[5];
    const float* bk = (const float*)d_in[6];
    const float* wv = (const float*)d_in[7];
    const float* bv = (const float*)d_in[8];
    const float* wp = (const float*)d_in[9];
    const float* bp = (const float*)d_in[10];
    float* out = (float*)d_out;

    bf16 *hnT, *qT, *kT, *v, *oT, *probs, *wb; float* attn; float2* stats;
    cudaGetSymbolAddress((void**)&hnT,   g_hnT);
    cudaGetSymbolAddress((void**)&qT,    g_qT);
    cudaGetSymbolAddress((void**)&kT,    g_kT);
    cudaGetSymbolAddress((void**)&v,     g_v);
    cudaGetSymbolAddress((void**)&oT,    g_oT);
    cudaGetSymbolAddress((void**)&attn,  g_attn);
    cudaGetSymbolAddress((void**)&probs, g_probs);
    cudaGetSymbolAddress((void**)&wb,    g_w);
    cudaGetSymbolAddress((void**)&stats, g_stats);
    bf16 *wqb = wb, *wkb = wb + C_ * C_, *wvb = wb + 2 * C_ * C_, *wpb = wb + 3 * C_ * C_;

    cudaFuncSetAttribute(gemm_bf<false, true,  false, true >, cudaFuncAttributeMaxDynamicSharedMemorySize, GEMM_SMEM);
    cudaFuncSetAttribute(gemm_bf<true,  false, false, true >, cudaFuncAttributeMaxDynamicSharedMemorySize, GEMM_SMEM);
    cudaFuncSetAttribute(gemm_bf<false, false, false, false>, cudaFuncAttributeMaxDynamicSharedMemorySize, GEMM_SMEM);
    cudaFuncSetAttribute(gemm_bf<false, false, false, true >, cudaFuncAttributeMaxDynamicSharedMemorySize, GEMM_SMEM);
    cudaFuncSetAttribute(gemm_bf<true,  false, true,  false>, cudaFuncAttributeMaxDynamicSharedMemorySize, GEMM_SMEM);

    const size_t sCH = (size_t)C_ * HW;
    const size_t sAA = (size_t)HW * HW;
    const float  scl = 1.f / sqrtf((float)C_);

    // 0) weights -> bf16 (one launch)
    cvt4_kernel<<<dim3(C_ * C_ / 1024, 4), 256>>>(wq, wk, wv, wp, wb);

    // 1) GroupNorm stats + normalize/transpose -> hnT (bf16)
    gn_stats_kernel<<<B_ * 32, 256>>>(x, stats);
    gn_transpose_kernel<<<dim3(HW / 32, C_ / 32, B_), 256>>>(x, gs, gb, stats, hnT);

    // 2) QT/KT[p,o] = hnT @ w^T + b        (M=1024, N=512, K=512) -> bf16
    {
        dim3 g(512 / BN, 1024 / BM, B_);
        gemm_bf<false, true, false, true><<<g, 128, GEMM_SMEM>>>(
            hnT, wqb, qT, bq, nullptr, 1024, 512, 512, sCH, 0, sCH, 0, 1.f);
        gemm_bf<false, true, false, true><<<g, 128, GEMM_SMEM>>>(
            hnT, wkb, kT, bk, nullptr, 1024, 512, 512, sCH, 0, sCH, 0, 1.f);
    }
    // 3) V[co,p] = wv @ hnT^T + bv         (M=512, N=1024, K=512) -> bf16
    {
        dim3 g(1024 / BN, 512 / BM, B_);
        gemm_bf<true, false, false, true><<<g, 128, GEMM_SMEM>>>(
            wvb, hnT, v, bv, nullptr, 512, 1024, 512, 0, sCH, sCH, 0, 1.f);
    }
    // 4) S = scl * QT @ KT^T               (M=1024, N=1024, K=512) -> fp32
    {
        dim3 g(1024 / BN, 1024 / BM, B_);
        gemm_bf<false, false, false, false><<<g, 128, GEMM_SMEM>>>(
            qT, kT, attn, nullptr, nullptr, 1024, 1024, 512, sCH, sCH, sAA, 0, scl);
    }
    // 5) softmax -> bf16 probs
    softmax_kernel<<<B_ * HW, 256>>>(attn, probs);

    // 6) OT[i,co] = probs @ V^T            (M=1024, N=512, K=1024) -> bf16
    {
        dim3 g(512 / BN, 1024 / BM, B_);
        gemm_bf<false, false, false, true><<<g, 128, GEMM_SMEM>>>(
            probs, v, oT, nullptr, nullptr, 1024, 512, 1024, sAA, sCH, sCH, 0, 1.f);
    }
    // 7) out[co,p] = wp @ OT^T + bp + x    (M=512, N=1024, K=512) -> fp32 + residual
    {
        dim3 g(1024 / BN, 512 / BM, B_);
        gemm_bf<true, false, true, false><<<g, 128, GEMM_SMEM>>>(
            wpb, oT, out, bp, x, 512, 1024, 512, 0, sCH, sCH, sCH, 1.f);
    }
}

// round 6
// speedup vs baseline: 8.9839x; 1.0759x over previous
#include <cuda_runtime.h>
#include <cuda_bf16.h>
#include <cstdint>
#include <math.h>

#define B_  32
#define C_  512
#define HW  1024
#define EPS 1e-5f

typedef __nv_bfloat16 bf16;

// ---------------------------------------------------------------------------
// Scratch (__device__ globals; allocation-free rule)
// ---------------------------------------------------------------------------
__device__ __align__(128) bf16  g_hnT[(size_t)B_ * HW * C_];   // [b, p, c]
__device__ __align__(128) bf16  g_qT [(size_t)B_ * HW * C_];   // [b, p, c]
__device__ __align__(128) bf16  g_kT [(size_t)B_ * HW * C_];   // [b, p, c]
__device__ __align__(128) bf16  g_v  [(size_t)B_ * C_ * HW];   // [b, c, p]
__device__ __align__(128) bf16  g_oT [(size_t)B_ * HW * C_];   // [b, p, c]
__device__ __align__(128) float g_attn [(size_t)B_ * HW * HW]; // fp32 scores
__device__ __align__(128) bf16  g_probs[(size_t)B_ * HW * HW]; // bf16 probs
__device__ __align__(128) bf16  g_w[4][C_ * C_];               // wq,wk,wv,wp bf16
__device__ float2 g_stats[B_ * 32];

// ---------------------------------------------------------------------------
// Helpers
// ---------------------------------------------------------------------------
__device__ __forceinline__ uint32_t smem_u32(const void* p) {
    uint32_t a;
    asm("{ .reg .u64 t; cvta.to.shared.u64 t, %1; cvt.u32.u64 %0, t; }" : "=r"(a) : "l"(p));
    return a;
}
__device__ __forceinline__ void cp16(uint32_t s, const void* g) {
    asm volatile("cp.async.cg.shared.global [%0], [%1], 16;" :: "r"(s), "l"(g));
}
__device__ __forceinline__ void ldsm4(uint32_t* r, uint32_t a) {
    asm volatile("ldmatrix.sync.aligned.m8n8.x4.shared.b16 {%0,%1,%2,%3}, [%4];"
                 : "=r"(r[0]), "=r"(r[1]), "=r"(r[2]), "=r"(r[3]) : "r"(a));
}
__device__ __forceinline__ void mma16(float* d, const uint32_t* a, uint32_t b0, uint32_t b1) {
    asm volatile("mma.sync.aligned.m16n8k16.row.col.f32.bf16.bf16.f32 "
        "{%0,%1,%2,%3}, {%4,%5,%6,%7}, {%8,%9}, {%0,%1,%2,%3};"
        : "+f"(d[0]), "+f"(d[1]), "+f"(d[2]), "+f"(d[3])
        : "r"(a[0]), "r"(a[1]), "r"(a[2]), "r"(a[3]), "r"(b0), "r"(b1));
}

// ---------------------------------------------------------------------------
// Weight fp32 -> bf16 conversion, all four weights in one launch
// ---------------------------------------------------------------------------
__global__ __launch_bounds__(256) void cvt4_kernel(
    const float* __restrict__ w0, const float* __restrict__ w1,
    const float* __restrict__ w2, const float* __restrict__ w3,
    bf16* __restrict__ dst)
{
    const float* src = (blockIdx.y == 0) ? w0 : (blockIdx.y == 1) ? w1
                     : (blockIdx.y == 2) ? w2 : w3;
    bf16* d = dst + (size_t)blockIdx.y * C_ * C_;
    int i = blockIdx.x * 256 + threadIdx.x;
    float4 v = *(const float4*)(src + i * 4);
    __nv_bfloat162* d2 = (__nv_bfloat162*)(d + i * 4);
    d2[0] = __floats2bfloat162_rn(v.x, v.y);
    d2[1] = __floats2bfloat162_rn(v.z, v.w);
}

// ---------------------------------------------------------------------------
// GroupNorm pass 1: stats per (batch, group)
// ---------------------------------------------------------------------------
__global__ __launch_bounds__(256) void gn_stats_kernel(const float* __restrict__ x,
                                                       float2* __restrict__ stats)
{
    int b = blockIdx.x >> 5, g = blockIdx.x & 31;
    const int n = 16 * HW;
    size_t base = ((size_t)b * C_ + (size_t)g * 16) * HW;
    const float4* x4 = (const float4*)(x + base);
    float s = 0.f, ss = 0.f;
    for (int i = threadIdx.x; i < n / 4; i += 256) {
        float4 v = x4[i];
        s  += v.x + v.y + v.z + v.w;
        ss += v.x * v.x + v.y * v.y + v.z * v.z + v.w * v.w;
    }
    __shared__ float sh_s[256], sh_ss[256];
    sh_s[threadIdx.x] = s; sh_ss[threadIdx.x] = ss;
    __syncthreads();
    for (int off = 128; off > 0; off >>= 1) {
        if (threadIdx.x < off) {
            sh_s[threadIdx.x]  += sh_s[threadIdx.x + off];
            sh_ss[threadIdx.x] += sh_ss[threadIdx.x + off];
        }
        __syncthreads();
    }
    if (threadIdx.x == 0) {
        float mean = sh_s[0] * (1.f / n);
        float var  = sh_ss[0] * (1.f / n) - mean * mean;
        stats[blockIdx.x] = make_float2(mean, rsqrtf(var + EPS));
    }
}

// ---------------------------------------------------------------------------
// GroupNorm pass 2: normalize + transpose -> hnT[b, p, c] (bf16)
// ---------------------------------------------------------------------------
__global__ __launch_bounds__(256) void gn_transpose_kernel(
    const float* __restrict__ x, const float* __restrict__ scale,
    const float* __restrict__ bias, const float2* __restrict__ stats,
    bf16* __restrict__ hnT)
{
    __shared__ float tile[32][33];
    int b = blockIdx.z, c0 = blockIdx.y * 32, p0 = blockIdx.x * 32;
    int lane = threadIdx.x & 31, r = threadIdx.x >> 5;
    #pragma unroll
    for (int i = 0; i < 4; i++) {
        int cl = r + i * 8, ch = c0 + cl;
        float2 st = stats[b * 32 + (ch >> 4)];
        float a = scale[ch] * st.y;
        float ad = bias[ch] - st.x * a;
        tile[cl][lane] = x[((size_t)b * C_ + ch) * HW + p0 + lane] * a + ad;
    }
    __syncthreads();
    #pragma unroll
    for (int i = 0; i < 4; i++) {
        int pl = r + i * 8;
        hnT[((size_t)b * HW + p0 + pl) * C_ + c0 + lane] = __float2bfloat16(tile[lane][pl]);
    }
}

// ---------------------------------------------------------------------------
// bf16 mma.sync GEMM: D[m,n] = alpha * sum_k A[m,k]*B[n,k]  (+bias) (+R)
// CTA tile 128x128x32, 128 threads (4 warps, 2x2), warp tile 64x64,
// 4-stage cp.async ring + register-level fragment double buffering.
// ---------------------------------------------------------------------------
#define BM 128
#define BN 128
#define BKB 32                         // k per tile (bf16 elems)
#define ROWB 80                        // bytes per smem row (64 data + 16 pad)
#define STAGE_B (BM * ROWB)            // 10240 bytes per operand stage
#define NSTAGE 4
#define GEMM_SMEM (2 * NSTAGE * STAGE_B)   // 81920 bytes

template<bool BIAS_M, bool BIAS_N, bool RES, bool OUTBF>
__global__ __launch_bounds__(128, 2) void gemm_bf(
    const bf16* __restrict__ A, const bf16* __restrict__ Bm, void* __restrict__ Cp,
    const float* __restrict__ bias, const float* __restrict__ R,
    int M, int N, int K, size_t sA, size_t sB, size_t sC, size_t sR, float alpha)
{
    extern __shared__ char smem[];
    uint32_t su = smem_u32(smem);
    const uint32_t BOFF = NSTAGE * STAGE_B;

    int tid = threadIdx.x, lane = tid & 31, wid = tid >> 5;
    int bz = blockIdx.z;
    A += sA * bz; Bm += sB * bz;
    if (RES) R += sR * bz;
    int m0 = blockIdx.y * BM, n0 = blockIdx.x * BN;

    int wm = (wid & 1) * 64;           // warp m-offset (64-wide)
    int wn = (wid >> 1) * 64;          // warp n-offset (64-wide)
    int g = lane >> 2, c = lane & 3;

    // ldmatrix per-lane offsets (bytes, within a stage)
    int a_row = (lane & 7) + ((lane >> 3) & 1) * 8;
    int a_kh  = lane >> 4;
    uint32_t aoff = (uint32_t)((wm + a_row) * ROWB + a_kh * 16);
    int b_row = (lane & 7) + ((lane >> 4) & 1) * 8;
    int b_kh  = (lane >> 3) & 1;
    uint32_t boffb = (uint32_t)((wn + b_row) * ROWB + b_kh * 16);

    float acc[4][8][4];
    #pragma unroll
    for (int mt = 0; mt < 4; mt++)
        #pragma unroll
        for (int nt = 0; nt < 8; nt++)
            #pragma unroll
            for (int r_ = 0; r_ < 4; r_++) acc[mt][nt][r_] = 0.f;

    int lrow = tid >> 2, lch = tid & 3;
    auto load_tile = [&](int kt, int st) {
        const bf16* Ag = A  + (size_t)m0 * K + kt * BKB;
        const bf16* Bg = Bm + (size_t)n0 * K + kt * BKB;
        uint32_t so = su + (uint32_t)st * STAGE_B;
        #pragma unroll
        for (int i = 0; i < 4; i++) {
            int row = lrow + i * 32;
            uint32_t off = (uint32_t)(row * ROWB + lch * 16);
            cp16(so + off,        Ag + (size_t)row * K + lch * 8);
            cp16(so + BOFF + off, Bg + (size_t)row * K + lch * 8);
        }
        asm volatile("cp.async.commit_group;" ::: "memory");
    };

    // fragment double buffers
    uint32_t af[2][4][4], bfr[2][4][4];
    auto ldsm_slab = [&](int st, int sl, int buf) {
        uint32_t abase = su + (uint32_t)st * STAGE_B;
        uint32_t bbase = abase + BOFF;
        uint32_t ko = (uint32_t)sl * 32;
        #pragma unroll
        for (int mt = 0; mt < 4; mt++)
            ldsm4(af[buf][mt], abase + aoff + mt * (16 * ROWB) + ko);
        #pragma unroll
        for (int pr = 0; pr < 4; pr++)
            ldsm4(bfr[buf][pr], bbase + boffb + pr * (16 * ROWB) + ko);
    };
    auto mma_slab = [&](int buf) {
        #pragma unroll
        for (int pr = 0; pr < 4; pr++)
            #pragma unroll
            for (int mt = 0; mt < 4; mt++) {
                mma16(acc[mt][pr * 2 + 0], af[buf][mt], bfr[buf][pr][0], bfr[buf][pr][1]);
                mma16(acc[mt][pr * 2 + 1], af[buf][mt], bfr[buf][pr][2], bfr[buf][pr][3]);
            }
    };

    load_tile(0, 0); load_tile(1, 1); load_tile(2, 2);
    asm volatile("cp.async.wait_group 2;" ::: "memory");
    __syncthreads();
    ldsm_slab(0, 0, 0);                      // tile 0, slab 0 -> buf 0

    const int KT = K / BKB;
    for (int kt = 0; kt < KT; kt++) {
        int cur = kt & 3;
        ldsm_slab(cur, 1, 1);                // slab 1 -> buf 1 (hidden by mma below)
        mma_slab(0);                         // slab 0
        if (kt + 3 < KT) load_tile(kt + 3, (kt + 3) & 3);
        if (kt + 1 < KT) {
            // wait until stage kt+1 has landed for every thread
            if (kt + 3 < KT)      asm volatile("cp.async.wait_group 2;" ::: "memory");
            else if (kt + 2 < KT) asm volatile("cp.async.wait_group 1;" ::: "memory");
            else                  asm volatile("cp.async.wait_group 0;" ::: "memory");
            __syncthreads();
            ldsm_slab((kt + 1) & 3, 0, 0);   // next tile slab 0 (hidden by mma below)
        }
        mma_slab(1);                         // slab 1
    }

    // epilogue
    #pragma unroll
    for (int mt = 0; mt < 4; mt++) {
        #pragma unroll
        for (int half = 0; half < 2; half++) {
            int m = m0 + wm + mt * 16 + g + half * 8;
            float bm = BIAS_M ? bias[m] : 0.f;
            #pragma unroll
            for (int nt = 0; nt < 8; nt++) {
                int n = n0 + wn + nt * 8 + c * 2;
                float v0 = acc[mt][nt][half * 2 + 0] * alpha + bm;
                float v1 = acc[mt][nt][half * 2 + 1] * alpha + bm;
                if (BIAS_N) { v0 += bias[n]; v1 += bias[n + 1]; }
                size_t off = (size_t)m * N + n;
                if (RES) { v0 += R[off]; v1 += R[off + 1]; }
                if (OUTBF) {
                    *(__nv_bfloat162*)((bf16*)Cp + sC * bz + off) = __floats2bfloat162_rn(v0, v1);
                } else {
                    *(float2*)((float*)Cp + sC * bz + off) = make_float2(v0, v1);
                }
            }
        }
    }
}

// ---------------------------------------------------------------------------
// Row softmax: fp32 scores in -> bf16 probs out
// ---------------------------------------------------------------------------
__global__ __launch_bounds__(256) void softmax_kernel(const float* __restrict__ attn,
                                                      bf16* __restrict__ probs)
{
    size_t row = blockIdx.x;
    const float4* p4 = (const float4*)(attn + row * HW);
    int tid = threadIdx.x;
    float4 v = p4[tid];
    __shared__ float sh[256];
    float m = fmaxf(fmaxf(v.x, v.y), fmaxf(v.z, v.w));
    sh[tid] = m; __syncthreads();
    for (int off = 128; off > 0; off >>= 1) {
        if (tid < off) sh[tid] = fmaxf(sh[tid], sh[tid + off]);
        __syncthreads();
    }
    m = sh[0];
    __syncthreads();
    v.x = expf(v.x - m); v.y = expf(v.y - m);
    v.z = expf(v.z - m); v.w = expf(v.w - m);
    sh[tid] = v.x + v.y + v.z + v.w;
    __syncthreads();
    for (int off = 128; off > 0; off >>= 1) {
        if (tid < off) sh[tid] += sh[tid + off];
        __syncthreads();
    }
    float inv = 1.f / sh[0];
    __nv_bfloat162* o2 = (__nv_bfloat162*)(probs + row * HW) + tid * 2;
    o2[0] = __floats2bfloat162_rn(v.x * inv, v.y * inv);
    o2[1] = __floats2bfloat162_rn(v.z * inv, v.w * inv);
}

// ---------------------------------------------------------------------------
extern "C" void kernel_launch(void* const* d_in, const int* in_sizes, int n_in,
                              void* d_out, int out_size)
{
    const float* x  = (const float*)d_in[0];
    const float* gs = (const float*)d_in[1];
    const float* gb = (const float*)d_in[2];
    const float* wq = (const float*)d_in[3];
    const float* bq = (const float*)d_in[4];
    const float* wk = (const float*)d_in[5];
    const float* bk = (const float*)d_in[6];
    const float* wv = (const float*)d_in[7];
    const float* bv = (const float*)d_in[8];
    const float* wp = (const float*)d_in[9];
    const float* bp = (const float*)d_in[10];
    float* out = (float*)d_out;

    bf16 *hnT, *qT, *kT, *v, *oT, *probs, *wb; float* attn; float2* stats;
    cudaGetSymbolAddress((void**)&hnT,   g_hnT);
    cudaGetSymbolAddress((void**)&qT,    g_qT);
    cudaGetSymbolAddress((void**)&kT,    g_kT);
    cudaGetSymbolAddress((void**)&v,     g_v);
    cudaGetSymbolAddress((void**)&oT,    g_oT);
    cudaGetSymbolAddress((void**)&attn,  g_attn);
    cudaGetSymbolAddress((void**)&probs, g_probs);
    cudaGetSymbolAddress((void**)&wb,    g_w);
    cudaGetSymbolAddress((void**)&stats, g_stats);
    bf16 *wqb = wb, *wkb = wb + C_ * C_, *wvb = wb + 2 * C_ * C_, *wpb = wb + 3 * C_ * C_;

    cudaFuncSetAttribute(gemm_bf<false, true,  false, true >, cudaFuncAttributeMaxDynamicSharedMemorySize, GEMM_SMEM);
    cudaFuncSetAttribute(gemm_bf<true,  false, false, true >, cudaFuncAttributeMaxDynamicSharedMemorySize, GEMM_SMEM);
    cudaFuncSetAttribute(gemm_bf<false, false, false, false>, cudaFuncAttributeMaxDynamicSharedMemorySize, GEMM_SMEM);
    cudaFuncSetAttribute(gemm_bf<false, false, false, true >, cudaFuncAttributeMaxDynamicSharedMemorySize, GEMM_SMEM);
    cudaFuncSetAttribute(gemm_bf<true,  false, true,  false>, cudaFuncAttributeMaxDynamicSharedMemorySize, GEMM_SMEM);

    const size_t sCH = (size_t)C_ * HW;
    const size_t sAA = (size_t)HW * HW;
    const float  scl = 1.f / sqrtf((float)C_);

    // 0) weights -> bf16 (one launch)
    cvt4_kernel<<<dim3(C_ * C_ / 1024, 4), 256>>>(wq, wk, wv, wp, wb);

    // 1) GroupNorm stats + normalize/transpose -> hnT (bf16)
    gn_stats_kernel<<<B_ * 32, 256>>>(x, stats);
    gn_transpose_kernel<<<dim3(HW / 32, C_ / 32, B_), 256>>>(x, gs, gb, stats, hnT);

    // 2) QT/KT[p,o] = hnT @ w^T + b        (M=1024, N=512, K=512) -> bf16
    {
        dim3 g(512 / BN, 1024 / BM, B_);
        gemm_bf<false, true, false, true><<<g, 128, GEMM_SMEM>>>(
            hnT, wqb, qT, bq, nullptr, 1024, 512, 512, sCH, 0, sCH, 0, 1.f);
        gemm_bf<false, true, false, true><<<g, 128, GEMM_SMEM>>>(
            hnT, wkb, kT, bk, nullptr, 1024, 512, 512, sCH, 0, sCH, 0, 1.f);
    }
    // 3) V[co,p] = wv @ hnT^T + bv         (M=512, N=1024, K=512) -> bf16
    {
        dim3 g(1024 / BN, 512 / BM, B_);
        gemm_bf<true, false, false, true><<<g, 128, GEMM_SMEM>>>(
            wvb, hnT, v, bv, nullptr, 512, 1024, 512, 0, sCH, sCH, 0, 1.f);
    }
    // 4) S = scl * QT @ KT^T               (M=1024, N=1024, K=512) -> fp32
    {
        dim3 g(1024 / BN, 1024 / BM, B_);
        gemm_bf<false, false, false, false><<<g, 128, GEMM_SMEM>>>(
            qT, kT, attn, nullptr, nullptr, 1024, 1024, 512, sCH, sCH, sAA, 0, scl);
    }
    // 5) softmax -> bf16 probs
    softmax_kernel<<<B_ * HW, 256>>>(attn, probs);

    // 6) OT[i,co] = probs @ V^T            (M=1024, N=512, K=1024) -> bf16
    {
        dim3 g(512 / BN, 1024 / BM, B_);
        gemm_bf<false, false, false, true><<<g, 128, GEMM_SMEM>>>(
            probs, v, oT, nullptr, nullptr, 1024, 512, 1024, sAA, sCH, sCH, 0, 1.f);
    }
    // 7) out[co,p] = wp @ OT^T + bp + x    (M=512, N=1024, K=512) -> fp32 + residual
    {
        dim3 g(1024 / BN, 512 / BM, B_);
        gemm_bf<true, false, true, false><<<g, 128, GEMM_SMEM>>>(
            wpb, oT, out, bp, x, 512, 1024, 512, 0, sCH, sCH, sCH, 1.f);
    }
}